// round 7
// baseline (speedup 1.0000x reference)
#include <cuda_runtime.h>
#include <math.h>

#define FULLMASK 0xFFFFFFFFu

// ---------------------------------------------------------------------------
// Focal_loss2 — fused focal loss, single kernel launch.
// Inputs: logits_a f32[2,2,128^3], logits_b f32[2,2,64^3], prob_a, prob_b,
//         connects_a i32, connects_b i32, coord_a i32[2,64,4], coord_b, fnames.
// Output f32[38]: [loss_pos, loss_neg, count_pos, count_neg, wsum_pos,
//                  wsum_neg, pred_prob_min[2,2,8]]
// ---------------------------------------------------------------------------

constexpr int ZC   = 32;                  // z-march chunk
constexpr int A_YT = 22, A_ZT = 4;        // D=128: y tiles (OUT=6), z chunks
constexpr int B_YT = 5,  B_ZT = 2;        // D=64 : y tiles (OUT=14), z chunks
constexpr int NBLK_A = A_YT * A_ZT * 4;   // 352
constexpr int NBLK_B = B_YT * B_ZT * 4;   // 40
constexpr int NBLK   = NBLK_A + NBLK_B;   // 392 neg blocks (+1 pos block)
constexpr int PLANE  = 256;               // float4 entries per z-plane (= threads)

// Cross-block state (no allocation allowed -> __device__ globals).
__device__ float2   g_part[NBLK];   // neg per-block partials {sum(w*nll), sum(w)}
__device__ double   g_posv[4];      // {loss0, w0, loss1, w1}
__device__ int      g_segres[32];   // segment-min results (int-ordered floats)
__device__ unsigned g_done;         // completion ticket; reset by finalize

__device__ __forceinline__ float softplusf_(float x) {
    return fmaxf(x, 0.f) + log1pf(__expf(-fabsf(x)));
}

// ---------------------------------------------------------------------------
// Negative branch: fused 3x3x3 local-max mask + focal weighting.
// Block = 256 threads. LPR = D/4 lanes per x-row, ROWS = 256/LPR y-rows
// (OUT = ROWS-2 output rows), marching z with a 3-plane smem ring of
// x-maxed + raw rows. Depth-2 register prefetch of logit planes; the
// conditional prob load is software-pipelined by one iteration so its DRAM
// latency is covered instead of stalling the per-plane barrier.
// ---------------------------------------------------------------------------
template<int D, int YT, int ZT>
__device__ __forceinline__ void neg_impl(const float* __restrict__ L,
                                         const float* __restrict__ P,
                                         int bid, int gbid,
                                         float4* sxm, float4* sraw, float* sred)
{
    constexpr int LPR  = D / 4;
    constexpr int ROWS = 256 / LPR;
    constexpr int OUT  = ROWS - 2;

    const int ytile = bid % YT;
    const int zc    = (bid / YT) % ZT;
    const int ba    = bid / (YT * ZT);

    const int tid = threadIdx.x;
    const int r   = tid / LPR;            // row within block (0..ROWS-1)
    const int xl  = tid % LPR;            // x lane
    const int x   = xl * 4;
    const int y0  = ytile * OUT;          // first output row
    const int z0  = zc * ZC;
    const int gy  = y0 - 1 + r;           // loaded row (with halo)
    const bool yin = (unsigned)gy < (unsigned)D;

    const size_t vol = (size_t)D * D * D;
    const float* Lb = L + (size_t)ba * vol;
    const float* Pb = P + (size_t)ba * vol;
    const long long rowoff = (long long)gy * D + x;

    auto loadPlane = [&](int z) -> float4 {
        float4 v = make_float4(-INFINITY, -INFINITY, -INFINITY, -INFINITY);
        if (yin && (unsigned)z < (unsigned)D)
            v = *reinterpret_cast<const float4*>(Lb + rowoff + (long long)z * D * D);
        return v;
    };

    // x-direction 3-max per component; neighbors across lanes via shuffle.
    auto xmax3 = [&](float4 v) -> float4 {
        float lft = __shfl_up_sync(FULLMASK, v.w, 1);
        float rgt = __shfl_down_sync(FULLMASK, v.x, 1);
        if (xl == 0)       lft = -INFINITY;   // x==0 edge (also fixes in-warp row wrap)
        if (xl == LPR - 1) rgt = -INFINITY;   // x==D-4 edge
        float4 m;
        m.x = fmaxf(lft,  fmaxf(v.x, v.y));
        m.y = fmaxf(v.x,  fmaxf(v.y, v.z));
        m.z = fmaxf(v.y,  fmaxf(v.z, v.w));
        m.w = fmaxf(rgt,  fmaxf(v.z, v.w));
        return m;
    };

    auto st = [&](int slot, float4 v, bool withRaw) {
        sxm[slot * PLANE + r * LPR + xl] = xmax3(v);
        if (withRaw) sraw[slot * PLANE + r * LPR + xl] = v;
    };

    // y-direction 3-max of x-maxed rows; only comp threads call (r+2 in-plane).
    auto pm3 = [&](int slot) -> float4 {
        float4 a = sxm[slot * PLANE + r * LPR + xl];
        float4 b = sxm[slot * PLANE + (r + 1) * LPR + xl];
        float4 c = sxm[slot * PLANE + (r + 2) * LPR + xl];
        float4 m;
        m.x = fmaxf(a.x, fmaxf(b.x, c.x));
        m.y = fmaxf(a.y, fmaxf(b.y, c.y));
        m.z = fmaxf(a.z, fmaxf(b.z, c.z));
        m.w = fmaxf(a.w, fmaxf(b.w, c.w));
        return m;
    };

    const int  gyo  = y0 + r;                                   // output row
    const bool comp = (r < OUT) && ((unsigned)gyo < (unsigned)D);
    const float* pp = Pb + ((size_t)(comp ? gyo : 0) * D + x);

    // ---- prologue
    {
        float4 v = loadPlane(z0 - 1);
        st(0, v, false);
    }
    float4 q0 = loadPlane(z0);
    float4 q1 = loadPlane(z0 + 1);
    __syncthreads();
    float4 pm_prev = make_float4(-INFINITY, -INFINITY, -INFINITY, -INFINITY);
    if (comp) pm_prev = pm3(0);
    st(1, q0, true);
    q0 = q1;
    q1 = loadPlane(z0 + 2);
    __syncthreads();
    float4 pm_cur = make_float4(-INFINITY, -INFINITY, -INFINITY, -INFINITY);
    float4 cen    = make_float4(0.f, 0.f, 0.f, 0.f);
    if (comp) {
        pm_cur = pm3(1);
        cen    = sraw[1 * PLANE + (r + 1) * LPR + xl];
    }

    float s_lw = 0.f, s_w = 0.f;

    // pending (deferred) prob-hit state from previous iteration
    bool  p0 = false, p1 = false, p2 = false, p3 = false;
    float4 ppg  = make_float4(0.f, 0.f, 0.f, 0.f);
    float4 pcen = make_float4(0.f, 0.f, 0.f, 0.f);

    auto consume = [&]() {
        if (p0 | p1 | p2 | p3) {
            if (p0 && ppg.x == -1.0f) {
                float s = 1.0f / (1.0f + __expf(-pcen.x));
                float w = s * s; s_w += w; s_lw += w * softplusf_(pcen.x);
            }
            if (p1 && ppg.y == -1.0f) {
                float s = 1.0f / (1.0f + __expf(-pcen.y));
                float w = s * s; s_w += w; s_lw += w * softplusf_(pcen.y);
            }
            if (p2 && ppg.z == -1.0f) {
                float s = 1.0f / (1.0f + __expf(-pcen.z));
                float w = s * s; s_w += w; s_lw += w * softplusf_(pcen.z);
            }
            if (p3 && ppg.w == -1.0f) {
                float s = 1.0f / (1.0f + __expf(-pcen.w));
                float w = s * s; s_w += w; s_lw += w * softplusf_(pcen.w);
            }
        }
    };

    // ---- main z loop: one barrier per plane
    for (int i = 0; i < ZC; ++i) {
        const int zout = z0 + i;
        const int snew = (i + 2) % 3;
        st(snew, q0, true);                       // plane zout+1
        q0 = q1;
        if (i + 3 <= ZC) q1 = loadPlane(z0 + i + 3);   // logits prefetch, depth 2
        __syncthreads();

        bool n0 = false, n1 = false, n2 = false, n3 = false;
        float4 npg = make_float4(0.f, 0.f, 0.f, 0.f);
        float4 pm_next = make_float4(-INFINITY, -INFINITY, -INFINITY, -INFINITY);
        if (comp) {
            pm_next = pm3(snew);
            float4 M;
            M.x = fmaxf(pm_prev.x, fmaxf(pm_cur.x, pm_next.x));
            M.y = fmaxf(pm_prev.y, fmaxf(pm_cur.y, pm_next.y));
            M.z = fmaxf(pm_prev.z, fmaxf(pm_cur.z, pm_next.z));
            M.w = fmaxf(pm_prev.w, fmaxf(pm_cur.w, pm_next.w));
            n0 = (M.x == cen.x); n1 = (M.y == cen.y);
            n2 = (M.z == cen.z); n3 = (M.w == cen.w);
            if (n0 | n1 | n2 | n3)                // issue now, consume next iter
                npg = *reinterpret_cast<const float4*>(pp + (size_t)zout * D * D);
        }
        // consume pending from previous iteration (its load has had ~1 full
        // iteration of barrier+LDS+FMAX cover)
        consume();
        ppg = npg; p0 = n0; p1 = n1; p2 = n2; p3 = n3; pcen = cen;

        pm_prev = pm_cur; pm_cur = pm_next;
        if (comp) cen = sraw[snew * PLANE + (r + 1) * LPR + xl];
    }
    consume();   // epilogue: last pending hit

    // ---- block reduction -> per-block partial
    #pragma unroll
    for (int o = 16; o; o >>= 1) {
        s_lw += __shfl_down_sync(FULLMASK, s_lw, o);
        s_w  += __shfl_down_sync(FULLMASK, s_w,  o);
    }
    const int lane = tid & 31, w = tid >> 5;
    __syncthreads();
    if (lane == 0) { sred[w] = s_lw; sred[8 + w] = s_w; }
    __syncthreads();
    if (tid == 0) {
        float a = 0.f, b = 0.f;
        #pragma unroll
        for (int i = 0; i < 8; i++) { a += sred[i]; b += sred[8 + i]; }
        g_part[gbid] = make_float2(a, b);
    }
}

// ---------------------------------------------------------------------------
// Positive branch (dedicated block, runs concurrently with neg blocks).
// Threads 0-127: level a (B*M = 128), threads 128-255: level b.
// ---------------------------------------------------------------------------
__device__ __forceinline__ void pos_impl(const float* __restrict__ La, const int* __restrict__ Ca,
                                         const int* __restrict__ coA,
                                         const float* __restrict__ Lb, const int* __restrict__ Cb,
                                         const int* __restrict__ coB,
                                         int* ssegmin, double* sdbl)
{
    const int t = threadIdx.x;
    if (t < 32) ssegmin[t] = 0x7F800000;   // +inf

    const int lvl = t >> 7, u = t & 127;
    const int b = u >> 6, m = u & 63;
    const float* L  = lvl ? Lb  : La;
    const int*   C  = lvl ? Cb  : Ca;
    const int*   CO = lvl ? coB : coA;
    const int    D  = lvl ? 64  : 128;

    const int* row = CO + (size_t)(b * 64 + m) * 4;
    int c0 = row[0], c1 = row[1], c2 = row[2], c3 = row[3];
    const bool valid = (c0 > -1);
    if (!valid) { c0 = c1 = c2 = c3 = 0; }
    const size_t idx = ((((size_t)(b * 2 + c0) * D + c1) * D + c2) * D + c3);
    const float lp = L[idx];
    const float s  = 1.0f / (1.0f + __expf(-lp));
    const float om = 1.0f - s;
    const float w1 = om * om;
    float loss = valid ? softplusf_(-lp) * w1 : 0.f;   // -log_sigmoid(lp)*w1 (w2==1)
    float w1v  = valid ? w1 : 0.f;

    __syncthreads();                                   // ssegmin init visible
    if (valid) {
        const int tag = C[idx];
        atomicMin(&ssegmin[lvl * 16 + b * 8 + tag], __float_as_int(w1));
    }

    #pragma unroll
    for (int o = 16; o; o >>= 1) {
        loss += __shfl_down_sync(FULLMASK, loss, o);
        w1v  += __shfl_down_sync(FULLMASK, w1v,  o);
    }
    const int lane = t & 31, wi = t >> 5;
    if (lane == 0) {
        sdbl[(lvl * 2 + 0) * 4 + (wi & 3)] = (double)loss;
        sdbl[(lvl * 2 + 1) * 4 + (wi & 3)] = (double)w1v;
    }
    __syncthreads();
    if (t < 4) {
        double acc = 0.0;
        #pragma unroll
        for (int i = 0; i < 4; i++) acc += sdbl[t * 4 + i];
        g_posv[t] = acc;   // {loss0, w0, loss1, w1}
    }
    if (t < 32) g_segres[t] = ssegmin[t];
}

// ---------------------------------------------------------------------------
// Finalize (executed by the last block to finish; cross-SM reads via __ldcg).
// ---------------------------------------------------------------------------
__device__ __forceinline__ void finalize(float* __restrict__ out, double* sdbl)
{
    const int t = threadIdx.x;
    double nl0 = 0, nw0 = 0, nl1 = 0, nw1 = 0;
    for (int i = t; i < NBLK; i += 256) {
        float2 p = __ldcg(&g_part[i]);
        if (i < NBLK_A) { nl0 += (double)p.x; nw0 += (double)p.y; }
        else            { nl1 += (double)p.x; nw1 += (double)p.y; }
    }
    #pragma unroll
    for (int o = 16; o; o >>= 1) {
        nl0 += __shfl_down_sync(FULLMASK, nl0, o);
        nw0 += __shfl_down_sync(FULLMASK, nw0, o);
        nl1 += __shfl_down_sync(FULLMASK, nl1, o);
        nw1 += __shfl_down_sync(FULLMASK, nw1, o);
    }
    const int lane = t & 31, wi = t >> 5;
    if (lane == 0) {
        sdbl[0 * 8 + wi] = nl0; sdbl[1 * 8 + wi] = nw0;
        sdbl[2 * 8 + wi] = nl1; sdbl[3 * 8 + wi] = nw1;
    }
    __syncthreads();
    if (t == 0) {
        double NL0 = 0, NW0 = 0, NL1 = 0, NW1 = 0;
        #pragma unroll
        for (int i = 0; i < 8; i++) {
            NL0 += sdbl[0 * 8 + i]; NW0 += sdbl[1 * 8 + i];
            NL1 += sdbl[2 * 8 + i]; NW1 += sdbl[3 * 8 + i];
        }
        const double pl0 = __ldcg(&g_posv[0]), pw0 = __ldcg(&g_posv[1]);
        const double pl1 = __ldcg(&g_posv[2]), pw1 = __ldcg(&g_posv[3]);
        // POS_FACTOR == NEG_FACTOR == [2, 1]
        out[0] = (float)(pl0 * 2.0 + pl1);   // cls_loss_pos
        out[1] = (float)(NL0 * 2.0 + NL1);   // cls_loss_neg
        out[2] = (float)(pw0       + pw1);   // count_pos
        out[3] = (float)(NW0       + NW1);   // count_neg
        out[4] = (float)(pw0 * 2.0 + pw1);   // wsum_pos
        out[5] = (float)(NW0 * 2.0 + NW1);   // wsum_neg
    }
    if (t < 32) {
        const int bits = __ldcg(&g_segres[t]);
        out[6 + t] = (bits == 0x7F800000) ? -1.0f : __int_as_float(bits);
    }
}

// ---------------------------------------------------------------------------
__global__ __launch_bounds__(256)
void fused_kernel(const float* __restrict__ La, const float* __restrict__ Pa,
                  const float* __restrict__ Lb, const float* __restrict__ Pb,
                  const int* __restrict__ Ca, const int* __restrict__ Cb,
                  const int* __restrict__ coA, const int* __restrict__ coB,
                  float* __restrict__ out)
{
    __shared__ float4 sxm[3 * PLANE];
    __shared__ float4 sraw[3 * PLANE];
    __shared__ float  sred[16];
    __shared__ double sdbl[32];
    __shared__ int    ssegmin[32];
    __shared__ bool   slast;

    const int bid = blockIdx.x;
    if (bid == NBLK)        pos_impl(La, Ca, coA, Lb, Cb, coB, ssegmin, sdbl);
    else if (bid < NBLK_A)  neg_impl<128, A_YT, A_ZT>(La, Pa, bid, bid, sxm, sraw, sred);
    else                    neg_impl<64,  B_YT, B_ZT>(Lb, Pb, bid - NBLK_A, bid, sxm, sraw, sred);

    // last-block ticket
    __threadfence();
    if (threadIdx.x == 0) {
        unsigned tk = atomicAdd(&g_done, 1u);
        slast = (tk == (unsigned)NBLK);   // NBLK+1 blocks total
    }
    __syncthreads();
    if (slast) {
        finalize(out, sdbl);
        __syncthreads();
        if (threadIdx.x == 0) g_done = 0;   // reset for next graph replay
    }
}

extern "C" void kernel_launch(void* const* d_in, const int* in_sizes, int n_in,
                              void* d_out, int out_size)
{
    (void)in_sizes; (void)n_in; (void)out_size;
    const float* logits_a = (const float*)d_in[0];
    const float* logits_b = (const float*)d_in[1];
    const float* prob_a   = (const float*)d_in[2];
    const float* prob_b   = (const float*)d_in[3];
    const int*   conn_a   = (const int*)d_in[4];
    const int*   conn_b   = (const int*)d_in[5];
    const int*   coord_a  = (const int*)d_in[6];
    const int*   coord_b  = (const int*)d_in[7];
    float* out = (float*)d_out;

    fused_kernel<<<NBLK + 1, 256>>>(logits_a, prob_a, logits_b, prob_b,
                                    conn_a, conn_b, coord_a, coord_b, out);
}

// round 8
// speedup vs baseline: 1.4523x; 1.4523x over previous
#include <cuda_runtime.h>
#include <math.h>

#define FULLMASK 0xFFFFFFFFu

// ---------------------------------------------------------------------------
// Focal_loss2 — fused focal loss, single launch, barrier-free z-march.
// Inputs: logits_a f32[2,2,128^3], logits_b f32[2,2,64^3], prob_a, prob_b,
//         connects_a i32, connects_b i32, coord_a i32[2,64,4], coord_b, fnames.
// Output f32[38]: [loss_pos, loss_neg, count_pos, count_neg, wsum_pos,
//                  wsum_neg, pred_prob_min[2,2,8]]
// ---------------------------------------------------------------------------

constexpr int ZC = 16;                    // z-march chunk
// level a: D=128, 8 rows/block (1 row per warp), 16 y-tiles, 8 z-chunks
constexpr int A_YT = 16, A_ZT = 8;
// level b: D=64, 16 rows/block (1 row per half-warp), 4 y-tiles, 4 z-chunks
constexpr int B_YT = 4,  B_ZT = 4;
constexpr int NBLK_A = A_YT * A_ZT * 4;   // 512
constexpr int NBLK_B = B_YT * B_ZT * 4;   // 64
constexpr int NBLK   = NBLK_A + NBLK_B;   // 576 neg blocks (+1 pos block)

// Cross-block state (no allocation allowed -> __device__ globals).
__device__ float2   g_part[NBLK];   // neg per-block partials {sum(w*nll), sum(w)}
__device__ double   g_posv[4];      // {loss0, w0, loss1, w1}
__device__ int      g_segres[32];   // segment-min results (int-ordered floats)
__device__ unsigned g_done;         // completion ticket; reset by finalize

__device__ __forceinline__ float softplusf_(float x) {
    return fmaxf(x, 0.f) + log1pf(__expf(-fabsf(x)));
}

__device__ __forceinline__ float4 f4max(float4 a, float4 b) {
    return make_float4(fmaxf(a.x, b.x), fmaxf(a.y, b.y),
                       fmaxf(a.z, b.z), fmaxf(a.w, b.w));
}

// ---------------------------------------------------------------------------
// Negative branch, warp-autonomous: each group of LPG lanes owns one output
// row y and marches z. 3 rows/plane loaded to registers; vertical max in
// registers; horizontal 3-max via 2 shuffles; z-max via 3 rolling plane-maxes.
// No shared memory, no barriers in the loop.
// ---------------------------------------------------------------------------
template<int D, int YT, int ZT>
__device__ __forceinline__ void neg_impl(const float* __restrict__ L,
                                         const float* __restrict__ P,
                                         int bid, int gbid, float* sred)
{
    constexpr int LPG = D / 4;        // lanes per row-group (32 for a, 16 for b)
    constexpr int GPB = 256 / LPG;    // rows per block (8 for a, 16 for b)
    constexpr int PL  = D * D;        // floats per z-plane

    const int ytile = bid % YT;
    const int zc    = (bid / YT) % ZT;
    const int ba    = bid / (YT * ZT);

    const int tid = threadIdx.x;
    const int g   = tid / LPG;        // group (row) index in block
    const int xl  = tid % LPG;        // x lane within group
    const int x   = xl * 4;
    const int y   = ytile * GPB + g;  // 0..D-1, always in range
    const int z0  = zc * ZC;

    const size_t vol = (size_t)D * D * D;
    const float* Lb = L + (size_t)ba * vol;
    const float* Pb = P + (size_t)ba * vol;

    const bool okm = (y > 0), okp = (y < D - 1);
    const float* pc  = Lb + (size_t)y * D + x;        // center row base (z=0)
    const float* pm1 = pc - D;                        // row y-1 (valid iff okm)
    const float* pp1 = pc + D;                        // row y+1 (valid iff okp)
    const float* pprob = Pb + (size_t)y * D + x;

    const float4 NEG4 = make_float4(-INFINITY, -INFINITY, -INFINITY, -INFINITY);

    auto ld3 = [&](int z, float4& r0, float4& r1, float4& r2) {
        if ((unsigned)z < (unsigned)D) {
            const size_t o = (size_t)z * PL;
            r1 = *reinterpret_cast<const float4*>(pc + o);
            r0 = okm ? *reinterpret_cast<const float4*>(pm1 + o) : NEG4;
            r2 = okp ? *reinterpret_cast<const float4*>(pp1 + o) : NEG4;
        } else { r0 = NEG4; r1 = NEG4; r2 = NEG4; }
    };

    // horizontal 3-max across the 4 components + lane neighbors (via shuffle).
    auto xmax3 = [&](float4 v) -> float4 {
        float lft = __shfl_up_sync(FULLMASK, v.w, 1);
        float rgt = __shfl_down_sync(FULLMASK, v.x, 1);
        if (xl == 0)       lft = -INFINITY;   // x edge (also isolates half-warp groups)
        if (xl == LPG - 1) rgt = -INFINITY;
        float4 m;
        m.x = fmaxf(lft,  fmaxf(v.x, v.y));
        m.y = fmaxf(v.x,  fmaxf(v.y, v.z));
        m.z = fmaxf(v.y,  fmaxf(v.z, v.w));
        m.w = fmaxf(rgt,  fmaxf(v.z, v.w));
        return m;
    };

    // ---- prologue: plane z0-1 and z0 maxes; plane z0+1 loads in flight
    float4 a0, a1, a2, b0, b1, b2;
    ld3(z0 - 1, a0, a1, a2);
    float4 pmm = xmax3(f4max(a0, f4max(a1, a2)));     // pm(z0-1)
    ld3(z0, a0, a1, a2);
    float4 cen = a1;                                   // raw center @ z0
    float4 pmc = xmax3(f4max(a0, f4max(a1, a2)));     // pm(z0)
    ld3(z0 + 1, b0, b1, b2);

    float s_lw = 0.f, s_w = 0.f;

    // ---- main z loop (no barriers)
    for (int i = 0; i < ZC; ++i) {
        const int zout = z0 + i;
        const float4 c0 = b0, c1 = b1, c2 = b2;        // plane zout+1 (arrived)
        ld3(zout + 2, b0, b1, b2);                     // issue next plane's loads
        const float4 pm_next = xmax3(f4max(c0, f4max(c1, c2)));
        const float4 M = f4max(pmm, f4max(pmc, pm_next));
        const bool m0 = (M.x == cen.x), m1 = (M.y == cen.y);
        const bool m2 = (M.z == cen.z), m3 = (M.w == cen.w);
        if (m0 | m1 | m2 | m3) {                       // ~15% of float4s
            const float4 pg = *reinterpret_cast<const float4*>(pprob + (size_t)zout * PL);
            if (m0 && pg.x == -1.0f) {
                float s = 1.0f / (1.0f + __expf(-cen.x));
                float w = s * s; s_w += w; s_lw += w * softplusf_(cen.x);
            }
            if (m1 && pg.y == -1.0f) {
                float s = 1.0f / (1.0f + __expf(-cen.y));
                float w = s * s; s_w += w; s_lw += w * softplusf_(cen.y);
            }
            if (m2 && pg.z == -1.0f) {
                float s = 1.0f / (1.0f + __expf(-cen.z));
                float w = s * s; s_w += w; s_lw += w * softplusf_(cen.z);
            }
            if (m3 && pg.w == -1.0f) {
                float s = 1.0f / (1.0f + __expf(-cen.w));
                float w = s * s; s_w += w; s_lw += w * softplusf_(cen.w);
            }
        }
        pmm = pmc; pmc = pm_next; cen = c1;
    }

    // ---- block reduction -> per-block partial (single barrier at the end)
    #pragma unroll
    for (int o = 16; o; o >>= 1) {
        s_lw += __shfl_down_sync(FULLMASK, s_lw, o);
        s_w  += __shfl_down_sync(FULLMASK, s_w,  o);
    }
    const int lane = tid & 31, w = tid >> 5;
    if (lane == 0) { sred[w] = s_lw; sred[8 + w] = s_w; }
    __syncthreads();
    if (tid == 0) {
        float a = 0.f, b = 0.f;
        #pragma unroll
        for (int i = 0; i < 8; i++) { a += sred[i]; b += sred[8 + i]; }
        g_part[gbid] = make_float2(a, b);
    }
}

// ---------------------------------------------------------------------------
// Positive branch (dedicated block). Threads 0-127: level a, 128-255: level b.
// ---------------------------------------------------------------------------
__device__ __forceinline__ void pos_impl(const float* __restrict__ La, const int* __restrict__ Ca,
                                         const int* __restrict__ coA,
                                         const float* __restrict__ Lb, const int* __restrict__ Cb,
                                         const int* __restrict__ coB,
                                         int* ssegmin, double* sdbl)
{
    const int t = threadIdx.x;
    if (t < 32) ssegmin[t] = 0x7F800000;   // +inf

    const int lvl = t >> 7, u = t & 127;
    const int b = u >> 6, m = u & 63;
    const float* L  = lvl ? Lb  : La;
    const int*   C  = lvl ? Cb  : Ca;
    const int*   CO = lvl ? coB : coA;
    const int    D  = lvl ? 64  : 128;

    const int* row = CO + (size_t)(b * 64 + m) * 4;
    int c0 = row[0], c1 = row[1], c2 = row[2], c3 = row[3];
    const bool valid = (c0 > -1);
    if (!valid) { c0 = c1 = c2 = c3 = 0; }
    const size_t idx = ((((size_t)(b * 2 + c0) * D + c1) * D + c2) * D + c3);
    const float lp = L[idx];
    const float s  = 1.0f / (1.0f + __expf(-lp));
    const float om = 1.0f - s;
    const float w1 = om * om;
    float loss = valid ? softplusf_(-lp) * w1 : 0.f;   // -log_sigmoid(lp)*w1 (w2==1)
    float w1v  = valid ? w1 : 0.f;

    __syncthreads();                                   // ssegmin init visible
    if (valid) {
        const int tag = C[idx];
        atomicMin(&ssegmin[lvl * 16 + b * 8 + tag], __float_as_int(w1));
    }

    #pragma unroll
    for (int o = 16; o; o >>= 1) {
        loss += __shfl_down_sync(FULLMASK, loss, o);
        w1v  += __shfl_down_sync(FULLMASK, w1v,  o);
    }
    const int lane = t & 31, wi = t >> 5;
    if (lane == 0) {
        sdbl[(lvl * 2 + 0) * 4 + (wi & 3)] = (double)loss;
        sdbl[(lvl * 2 + 1) * 4 + (wi & 3)] = (double)w1v;
    }
    __syncthreads();
    if (t < 4) {
        double acc = 0.0;
        #pragma unroll
        for (int i = 0; i < 4; i++) acc += sdbl[t * 4 + i];
        g_posv[t] = acc;   // {loss0, w0, loss1, w1}
    }
    if (t < 32) g_segres[t] = ssegmin[t];
}

// ---------------------------------------------------------------------------
// Finalize (last block to finish; cross-SM reads via __ldcg).
// ---------------------------------------------------------------------------
__device__ __forceinline__ void finalize(float* __restrict__ out, double* sdbl)
{
    const int t = threadIdx.x;
    double nl0 = 0, nw0 = 0, nl1 = 0, nw1 = 0;
    for (int i = t; i < NBLK; i += 256) {
        float2 p = __ldcg(&g_part[i]);
        if (i < NBLK_A) { nl0 += (double)p.x; nw0 += (double)p.y; }
        else            { nl1 += (double)p.x; nw1 += (double)p.y; }
    }
    #pragma unroll
    for (int o = 16; o; o >>= 1) {
        nl0 += __shfl_down_sync(FULLMASK, nl0, o);
        nw0 += __shfl_down_sync(FULLMASK, nw0, o);
        nl1 += __shfl_down_sync(FULLMASK, nl1, o);
        nw1 += __shfl_down_sync(FULLMASK, nw1, o);
    }
    const int lane = t & 31, wi = t >> 5;
    if (lane == 0) {
        sdbl[0 * 8 + wi] = nl0; sdbl[1 * 8 + wi] = nw0;
        sdbl[2 * 8 + wi] = nl1; sdbl[3 * 8 + wi] = nw1;
    }
    __syncthreads();
    if (t == 0) {
        double NL0 = 0, NW0 = 0, NL1 = 0, NW1 = 0;
        #pragma unroll
        for (int i = 0; i < 8; i++) {
            NL0 += sdbl[0 * 8 + i]; NW0 += sdbl[1 * 8 + i];
            NL1 += sdbl[2 * 8 + i]; NW1 += sdbl[3 * 8 + i];
        }
        const double pl0 = __ldcg(&g_posv[0]), pw0 = __ldcg(&g_posv[1]);
        const double pl1 = __ldcg(&g_posv[2]), pw1 = __ldcg(&g_posv[3]);
        // POS_FACTOR == NEG_FACTOR == [2, 1]
        out[0] = (float)(pl0 * 2.0 + pl1);   // cls_loss_pos
        out[1] = (float)(NL0 * 2.0 + NL1);   // cls_loss_neg
        out[2] = (float)(pw0       + pw1);   // count_pos
        out[3] = (float)(NW0       + NW1);   // count_neg
        out[4] = (float)(pw0 * 2.0 + pw1);   // wsum_pos
        out[5] = (float)(NW0 * 2.0 + NW1);   // wsum_neg
    }
    if (t < 32) {
        const int bits = __ldcg(&g_segres[t]);
        out[6 + t] = (bits == 0x7F800000) ? -1.0f : __int_as_float(bits);
    }
}

// ---------------------------------------------------------------------------
__global__ __launch_bounds__(256, 4)
void fused_kernel(const float* __restrict__ La, const float* __restrict__ Pa,
                  const float* __restrict__ Lb, const float* __restrict__ Pb,
                  const int* __restrict__ Ca, const int* __restrict__ Cb,
                  const int* __restrict__ coA, const int* __restrict__ coB,
                  float* __restrict__ out)
{
    __shared__ float  sred[16];
    __shared__ double sdbl[32];
    __shared__ int    ssegmin[32];
    __shared__ bool   slast;

    const int bid = blockIdx.x;
    if (bid == NBLK)        pos_impl(La, Ca, coA, Lb, Cb, coB, ssegmin, sdbl);
    else if (bid < NBLK_A)  neg_impl<128, A_YT, A_ZT>(La, Pa, bid, bid, sred);
    else                    neg_impl<64,  B_YT, B_ZT>(Lb, Pb, bid - NBLK_A, bid, sred);

    // last-block ticket
    __threadfence();
    if (threadIdx.x == 0) {
        unsigned tk = atomicAdd(&g_done, 1u);
        slast = (tk == (unsigned)NBLK);   // NBLK+1 blocks total
    }
    __syncthreads();
    if (slast) {
        finalize(out, sdbl);
        __syncthreads();
        if (threadIdx.x == 0) g_done = 0;   // reset for next graph replay
    }
}

extern "C" void kernel_launch(void* const* d_in, const int* in_sizes, int n_in,
                              void* d_out, int out_size)
{
    (void)in_sizes; (void)n_in; (void)out_size;
    const float* logits_a = (const float*)d_in[0];
    const float* logits_b = (const float*)d_in[1];
    const float* prob_a   = (const float*)d_in[2];
    const float* prob_b   = (const float*)d_in[3];
    const int*   conn_a   = (const int*)d_in[4];
    const int*   conn_b   = (const int*)d_in[5];
    const int*   coord_a  = (const int*)d_in[6];
    const int*   coord_b  = (const int*)d_in[7];
    float* out = (float*)d_out;

    fused_kernel<<<NBLK + 1, 256>>>(logits_a, prob_a, logits_b, prob_b,
                                    conn_a, conn_b, coord_a, coord_b, out);
}